// round 1
// baseline (speedup 1.0000x reference)
#include <cuda_runtime.h>

#define Bn  2
#define CO  8
#define CI  8
#define DD  8
#define GH  16
#define GW  16
#define HH  512
#define WW  512
#define TW  256   // threads per block = columns per tile
#define THR 4     // rows per thread
#define NY  3     // y grid values cached (<=2 cells per 4-row tile)
#define NX  10    // x grid values cached (<=9 cells per 256-col tile)

__device__ __forceinline__ unsigned long long ffma2(unsigned long long a,
                                                    unsigned long long b,
                                                    unsigned long long c) {
    unsigned long long d;
    asm("fma.rn.f32x2 %0, %1, %2, %3;" : "=l"(d) : "l"(a), "l"(b), "l"(c));
    return d;
}
__device__ __forceinline__ unsigned long long pack2(float lo, float hi) {
    unsigned long long r;
    asm("mov.b64 %0, {%1, %2};" : "=l"(r) : "f"(lo), "f"(hi));
    return r;
}
__device__ __forceinline__ float2 unpack2(unsigned long long v) {
    float2 f;
    asm("mov.b64 {%0, %1}, %2;" : "=f"(f.x), "=f"(f.y) : "l"(v));
    return f;
}

__global__ __launch_bounds__(TW) void bsa_kernel(
    const float* __restrict__ grid,
    const float* __restrict__ guide,
    const float* __restrict__ inp,
    float* __restrict__ out)
{
    // smem layout: [yy][xx][k][d][co], co fastest (8 floats = 32B, 16B-aligned)
    __shared__ __align__(16) float sg[NY * NX * 2 * DD * CO];

    const int b  = blockIdx.z;
    const int w0 = blockIdx.x * TW;
    const int h0 = blockIdx.y * THR;
    const int t  = threadIdx.x;
    const float s = 15.0f / 511.0f;   // (GH-1)/(H-1) == (GW-1)/(W-1)

    int ybase = (int)((float)h0 * s); if (ybase > GH - 2) ybase = GH - 2;
    int xbase = (int)((float)w0 * s); if (xbase > GW - 2) xbase = GW - 2;

    // ---- stage grid slice into smem ----
    const float* gptr0 = grid + (size_t)b * (CO * 2 * DD * GH * GW);
    #pragma unroll
    for (int i = t; i < NY * NX * 2 * DD * CO; i += TW) {
        int xx = i % NX;
        int r  = i / NX;
        int yy = r % NY;  r /= NY;
        int d  = r % DD;  r /= DD;
        int k  = r % 2;
        int co = r / 2;
        int gy = ybase + yy; if (gy > GH - 1) gy = GH - 1;
        int gx = xbase + xx; if (gx > GW - 1) gx = GW - 1;
        sg[(((yy * NX + xx) * 2 + k) * DD + d) * CO + co] =
            gptr0[(((co * 2 + k) * DD + d) * GH + gy) * GW + gx];
    }
    __syncthreads();

    const int w = w0 + t;
    float xp = (float)w * s;
    int   x0 = (int)xp; if (x0 > GW - 2) x0 = GW - 2;
    float wx = xp - (float)x0;
    const int lx = x0 - xbase;

    const size_t hw = (size_t)HH * WW;
    const float* gup  = guide + (size_t)b * CI * hw + (size_t)h0 * WW + w;
    const float* inpp = inp   + (size_t)b * CI * hw + (size_t)h0 * WW + w;
    float*       outp = out   + (size_t)b * CO * hw + (size_t)h0 * WW + w;

    #pragma unroll
    for (int r = 0; r < THR; r++) {
        const int h = h0 + r;
        float yp = (float)h * s;
        int   y0 = (int)yp; if (y0 > GH - 2) y0 = GH - 2;
        float wy = yp - (float)y0;
        const int ly = y0 - ybase;

        // ---- build A[d] = sum_ci in*phi_d(z),  Bv[d] = (1/8) sum_ci phi_d(z) ----
        float A[DD], Bv[DD];
        #pragma unroll
        for (int d = 0; d < DD; d++) { A[d] = 0.f; Bv[d] = 0.f; }

        #pragma unroll
        for (int ci = 0; ci < CI; ci++) {
            float g = gup [ci * hw + (size_t)r * WW];
            float v = inpp[ci * hw + (size_t)r * WW];
            float zp = fminf(fmaxf(g * 7.0f, 0.0f), 7.0f);
            #pragma unroll
            for (int d = 0; d < DD; d++) {
                float wd = fmaxf(0.0f, 1.0f - fabsf(zp - (float)d));
                A[d]  = fmaf(v, wd, A[d]);
                Bv[d] += wd;
            }
        }

        unsigned long long AA[DD], BB[DD];
        #pragma unroll
        for (int d = 0; d < DD; d++) {
            AA[d] = pack2(A[d], A[d]);
            float bb = Bv[d] * 0.125f;   // mean over C_in
            BB[d] = pack2(bb, bb);
        }

        // ---- contract against 4 (y,x) corners; co pairs in f32x2 ----
        unsigned long long o0 = 0ull, o1 = 0ull, o2 = 0ull, o3 = 0ull;
        const float cwy[2] = {1.0f - wy, wy};
        const float cwx[2] = {1.0f - wx, wx};

        #pragma unroll
        for (int cy = 0; cy < 2; cy++) {
            #pragma unroll
            for (int cxi = 0; cxi < 2; cxi++) {
                const int cell = (((ly + cy) * NX + (lx + cxi)) * 2) * DD * CO;
                unsigned long long t0 = 0ull, t1 = 0ull, t2 = 0ull, t3 = 0ull;
                #pragma unroll
                for (int d = 0; d < DD; d++) {
                    const ulonglong2* pw =
                        reinterpret_cast<const ulonglong2*>(&sg[cell + d * CO]);
                    const ulonglong2* pb =
                        reinterpret_cast<const ulonglong2*>(&sg[cell + (DD + d) * CO]);
                    ulonglong2 wA = pw[0];   // (co0,co1),(co2,co3)
                    ulonglong2 wB = pw[1];   // (co4,co5),(co6,co7)
                    ulonglong2 bA = pb[0];
                    ulonglong2 bB = pb[1];
                    t0 = ffma2(wA.x, AA[d], t0);
                    t1 = ffma2(wA.y, AA[d], t1);
                    t2 = ffma2(wB.x, AA[d], t2);
                    t3 = ffma2(wB.y, AA[d], t3);
                    t0 = ffma2(bA.x, BB[d], t0);
                    t1 = ffma2(bA.y, BB[d], t1);
                    t2 = ffma2(bB.x, BB[d], t2);
                    t3 = ffma2(bB.y, BB[d], t3);
                }
                float wc = cwy[cy] * cwx[cxi];
                unsigned long long WC = pack2(wc, wc);
                o0 = ffma2(t0, WC, o0);
                o1 = ffma2(t1, WC, o1);
                o2 = ffma2(t2, WC, o2);
                o3 = ffma2(t3, WC, o3);
            }
        }

        float2 f0 = unpack2(o0), f1 = unpack2(o1), f2 = unpack2(o2), f3 = unpack2(o3);
        outp[0 * hw + (size_t)r * WW] = f0.x;
        outp[1 * hw + (size_t)r * WW] = f0.y;
        outp[2 * hw + (size_t)r * WW] = f1.x;
        outp[3 * hw + (size_t)r * WW] = f1.y;
        outp[4 * hw + (size_t)r * WW] = f2.x;
        outp[5 * hw + (size_t)r * WW] = f2.y;
        outp[6 * hw + (size_t)r * WW] = f3.x;
        outp[7 * hw + (size_t)r * WW] = f3.y;
    }
}

extern "C" void kernel_launch(void* const* d_in, const int* in_sizes, int n_in,
                              void* d_out, int out_size) {
    const float* grid  = (const float*)d_in[0];   // (2,8,2,8,16,16)
    const float* guide = (const float*)d_in[1];   // (2,8,512,512)
    const float* inp   = (const float*)d_in[2];   // (2,8,512,512)
    float* out = (float*)d_out;                   // (2,8,512,512)

    dim3 g(WW / TW, HH / THR, Bn);   // (2, 128, 2) = 512 blocks
    bsa_kernel<<<g, TW>>>(grid, guide, inp, out);
}

// round 2
// speedup vs baseline: 1.0049x; 1.0049x over previous
#include <cuda_runtime.h>

#define Bn  2
#define CO  8
#define CI  8
#define DD  8
#define GH  16
#define GW  16
#define HH  512
#define WW  512
#define TW  256   // threads per block = columns per tile
#define THR 4     // rows per thread
#define NY  3     // y grid values cached (<=2 cells per 4-row tile)
#define NX  10    // x grid values cached (<=9 cells per 256-col tile)

__device__ __forceinline__ unsigned long long ffma2(unsigned long long a,
                                                    unsigned long long b,
                                                    unsigned long long c) {
    unsigned long long d;
    asm("fma.rn.f32x2 %0, %1, %2, %3;" : "=l"(d) : "l"(a), "l"(b), "l"(c));
    return d;
}
__device__ __forceinline__ unsigned long long pack2(float lo, float hi) {
    unsigned long long r;
    asm("mov.b64 %0, {%1, %2};" : "=l"(r) : "f"(lo), "f"(hi));
    return r;
}
__device__ __forceinline__ float2 unpack2(unsigned long long v) {
    float2 f;
    asm("mov.b64 {%0, %1}, %2;" : "=f"(f.x), "=f"(f.y) : "l"(v));
    return f;
}

__global__ __launch_bounds__(TW) void bsa_kernel(
    const float* __restrict__ grid,
    const float* __restrict__ guide,
    const float* __restrict__ inp,
    float* __restrict__ out)
{
    // smem layout: [yy][xx][k][d][co], co fastest (8 floats = 32B, 16B-aligned)
    __shared__ __align__(16) float sg[NY * NX * 2 * DD * CO];

    const int b  = blockIdx.z;
    const int w0 = blockIdx.x * TW;
    const int h0 = blockIdx.y * THR;
    const int t  = threadIdx.x;
    const float s = 15.0f / 511.0f;   // (GH-1)/(H-1) == (GW-1)/(W-1)

    int ybase = (int)((float)h0 * s); if (ybase > GH - 2) ybase = GH - 2;
    int xbase = (int)((float)w0 * s); if (xbase > GW - 2) xbase = GW - 2;

    // ---- stage grid slice into smem ----
    const float* gptr0 = grid + (size_t)b * (CO * 2 * DD * GH * GW);
    #pragma unroll
    for (int i = t; i < NY * NX * 2 * DD * CO; i += TW) {
        int xx = i % NX;
        int r  = i / NX;
        int yy = r % NY;  r /= NY;
        int d  = r % DD;  r /= DD;
        int k  = r % 2;
        int co = r / 2;
        int gy = ybase + yy; if (gy > GH - 1) gy = GH - 1;
        int gx = xbase + xx; if (gx > GW - 1) gx = GW - 1;
        sg[(((yy * NX + xx) * 2 + k) * DD + d) * CO + co] =
            gptr0[(((co * 2 + k) * DD + d) * GH + gy) * GW + gx];
    }
    __syncthreads();

    const int w = w0 + t;
    float xp = (float)w * s;
    int   x0 = (int)xp; if (x0 > GW - 2) x0 = GW - 2;
    float wx = xp - (float)x0;
    const int lx = x0 - xbase;

    const size_t hw = (size_t)HH * WW;
    const float* gup  = guide + (size_t)b * CI * hw + (size_t)h0 * WW + w;
    const float* inpp = inp   + (size_t)b * CI * hw + (size_t)h0 * WW + w;
    float*       outp = out   + (size_t)b * CO * hw + (size_t)h0 * WW + w;

    #pragma unroll
    for (int r = 0; r < THR; r++) {
        const int h = h0 + r;
        float yp = (float)h * s;
        int   y0 = (int)yp; if (y0 > GH - 2) y0 = GH - 2;
        float wy = yp - (float)y0;
        const int ly = y0 - ybase;

        // ---- build A[d] = sum_ci in*phi_d(z),  Bv[d] = (1/8) sum_ci phi_d(z) ----
        float A[DD], Bv[DD];
        #pragma unroll
        for (int d = 0; d < DD; d++) { A[d] = 0.f; Bv[d] = 0.f; }

        #pragma unroll
        for (int ci = 0; ci < CI; ci++) {
            float g = gup [ci * hw + (size_t)r * WW];
            float v = inpp[ci * hw + (size_t)r * WW];
            float zp = fminf(fmaxf(g * 7.0f, 0.0f), 7.0f);
            #pragma unroll
            for (int d = 0; d < DD; d++) {
                float wd = fmaxf(0.0f, 1.0f - fabsf(zp - (float)d));
                A[d]  = fmaf(v, wd, A[d]);
                Bv[d] += wd;
            }
        }

        unsigned long long AA[DD], BB[DD];
        #pragma unroll
        for (int d = 0; d < DD; d++) {
            AA[d] = pack2(A[d], A[d]);
            float bb = Bv[d] * 0.125f;   // mean over C_in
            BB[d] = pack2(bb, bb);
        }

        // ---- contract against 4 (y,x) corners; co pairs in f32x2 ----
        unsigned long long o0 = 0ull, o1 = 0ull, o2 = 0ull, o3 = 0ull;
        const float cwy[2] = {1.0f - wy, wy};
        const float cwx[2] = {1.0f - wx, wx};

        #pragma unroll
        for (int cy = 0; cy < 2; cy++) {
            #pragma unroll
            for (int cxi = 0; cxi < 2; cxi++) {
                const int cell = (((ly + cy) * NX + (lx + cxi)) * 2) * DD * CO;
                unsigned long long t0 = 0ull, t1 = 0ull, t2 = 0ull, t3 = 0ull;
                #pragma unroll
                for (int d = 0; d < DD; d++) {
                    const ulonglong2* pw =
                        reinterpret_cast<const ulonglong2*>(&sg[cell + d * CO]);
                    const ulonglong2* pb =
                        reinterpret_cast<const ulonglong2*>(&sg[cell + (DD + d) * CO]);
                    ulonglong2 wA = pw[0];   // (co0,co1),(co2,co3)
                    ulonglong2 wB = pw[1];   // (co4,co5),(co6,co7)
                    ulonglong2 bA = pb[0];
                    ulonglong2 bB = pb[1];
                    t0 = ffma2(wA.x, AA[d], t0);
                    t1 = ffma2(wA.y, AA[d], t1);
                    t2 = ffma2(wB.x, AA[d], t2);
                    t3 = ffma2(wB.y, AA[d], t3);
                    t0 = ffma2(bA.x, BB[d], t0);
                    t1 = ffma2(bA.y, BB[d], t1);
                    t2 = ffma2(bB.x, BB[d], t2);
                    t3 = ffma2(bB.y, BB[d], t3);
                }
                float wc = cwy[cy] * cwx[cxi];
                unsigned long long WC = pack2(wc, wc);
                o0 = ffma2(t0, WC, o0);
                o1 = ffma2(t1, WC, o1);
                o2 = ffma2(t2, WC, o2);
                o3 = ffma2(t3, WC, o3);
            }
        }

        float2 f0 = unpack2(o0), f1 = unpack2(o1), f2 = unpack2(o2), f3 = unpack2(o3);
        outp[0 * hw + (size_t)r * WW] = f0.x;
        outp[1 * hw + (size_t)r * WW] = f0.y;
        outp[2 * hw + (size_t)r * WW] = f1.x;
        outp[3 * hw + (size_t)r * WW] = f1.y;
        outp[4 * hw + (size_t)r * WW] = f2.x;
        outp[5 * hw + (size_t)r * WW] = f2.y;
        outp[6 * hw + (size_t)r * WW] = f3.x;
        outp[7 * hw + (size_t)r * WW] = f3.y;
    }
}

extern "C" void kernel_launch(void* const* d_in, const int* in_sizes, int n_in,
                              void* d_out, int out_size) {
    const float* grid  = (const float*)d_in[0];   // (2,8,2,8,16,16)
    const float* guide = (const float*)d_in[1];   // (2,8,512,512)
    const float* inp   = (const float*)d_in[2];   // (2,8,512,512)
    float* out = (float*)d_out;                   // (2,8,512,512)

    dim3 g(WW / TW, HH / THR, Bn);   // (2, 128, 2) = 512 blocks
    bsa_kernel<<<g, TW>>>(grid, guide, inp, out);
}

// round 3
// speedup vs baseline: 1.4891x; 1.4819x over previous
#include <cuda_runtime.h>

#define Bn  2
#define CO  8
#define CI  8
#define DD  8
#define GH  16
#define GW  16
#define HH  512
#define WW  512
#define TW  256   // threads per block = columns per tile
#define THR 4     // rows per thread (tile height)
#define NY  3     // y grid rows cached (<=2 cells per 4-row tile)
#define NX  10    // x grid cols cached (<=9 cells per 256-col tile)

__device__ __forceinline__ unsigned long long ffma2(unsigned long long a,
                                                    unsigned long long b,
                                                    unsigned long long c) {
    unsigned long long d;
    asm("fma.rn.f32x2 %0, %1, %2, %3;" : "=l"(d) : "l"(a), "l"(b), "l"(c));
    return d;
}
__device__ __forceinline__ unsigned long long fmul2(unsigned long long a,
                                                    unsigned long long b) {
    unsigned long long d;
    asm("mul.rn.f32x2 %0, %1, %2;" : "=l"(d) : "l"(a), "l"(b));
    return d;
}
__device__ __forceinline__ unsigned long long pack2(float lo, float hi) {
    unsigned long long r;
    asm("mov.b64 %0, {%1, %2};" : "=l"(r) : "f"(lo), "f"(hi));
    return r;
}
__device__ __forceinline__ float2 unpack2(unsigned long long v) {
    float2 f;
    asm("mov.b64 {%0, %1}, %2;" : "=f"(f.x), "=f"(f.y) : "l"(v));
    return f;
}

__global__ __launch_bounds__(TW) void bsa_kernel(
    const float* __restrict__ grid,
    const float* __restrict__ guide,
    const float* __restrict__ inp,
    float* __restrict__ out)
{
    // raw grid slice: [yy][xx][k][d][co], co fastest
    __shared__ __align__(16) float sg[NY * NX * 2 * DD * CO];
    // y-folded coefficients per tile row: [r][xx][d][k][co], co fastest
    // per (xx,d): 16 floats = 64 B contiguous (w0..7, b0..7)
    __shared__ __align__(16) float gy[THR * NX * DD * 2 * CO];

    const int b  = blockIdx.z;
    const int w0 = blockIdx.x * TW;
    const int h0 = blockIdx.y * THR;
    const int t  = threadIdx.x;
    const float s = 15.0f / 511.0f;

    int ybase = (int)((float)h0 * s); if (ybase > GH - 2) ybase = GH - 2;
    int xbase = (int)((float)w0 * s); if (xbase > GW - 2) xbase = GW - 2;

    // ---- stage raw grid slice (coalesced-ish LDG) ----
    const float* gptr0 = grid + (size_t)b * (CO * 2 * DD * GH * GW);
    #pragma unroll
    for (int i = t; i < NY * NX * 2 * DD * CO; i += TW) {
        int xx = i % NX;
        int r  = i / NX;
        int yy = r % NY;  r /= NY;
        int d  = r % DD;  r /= DD;
        int k  = r % 2;
        int co = r / 2;
        int gyy = ybase + yy; if (gyy > GH - 1) gyy = GH - 1;
        int gx  = xbase + xx; if (gx  > GW - 1) gx  = GW - 1;
        sg[(((yy * NX + xx) * 2 + k) * DD + d) * CO + co] =
            gptr0[(((co * 2 + k) * DD + d) * GH + gyy) * GW + gx];
    }
    __syncthreads();

    // ---- y-fold: gy[r][xx][d][k][co] = (1-wy_r)*sg[ly] + wy_r*sg[ly+1] ----
    #pragma unroll
    for (int j = t; j < THR * NX * DD * 2 * CO; j += TW) {
        int co = j & 7;
        int k  = (j >> 3) & 1;
        int d  = (j >> 4) & 7;
        int v  = j >> 7;          // r*NX + xx, in [0, THR*NX)
        int xx = v % NX;
        int r  = v / NX;
        int h  = h0 + r;
        float yp = (float)h * s;
        int   y0 = (int)yp; if (y0 > GH - 2) y0 = GH - 2;
        float wy = yp - (float)y0;
        int   ly = y0 - ybase;
        float v0 = sg[(((ly       * NX + xx) * 2 + k) * DD + d) * CO + co];
        float v1 = sg[((((ly + 1) * NX + xx) * 2 + k) * DD + d) * CO + co];
        gy[j] = v0 + wy * (v1 - v0);
    }
    __syncthreads();

    const int w = w0 + t;
    float xp = (float)w * s;
    int   x0 = (int)xp; if (x0 > GW - 2) x0 = GW - 2;
    float wx = xp - (float)x0;
    const int lx = x0 - xbase;
    const unsigned long long WX  = pack2(wx, wx);
    const unsigned long long WX1 = pack2(1.0f - wx, 1.0f - wx);

    const size_t hw = (size_t)HH * WW;
    const float* gup  = guide + (size_t)b * CI * hw + (size_t)h0 * WW + w;
    const float* inpp = inp   + (size_t)b * CI * hw + (size_t)h0 * WW + w;
    float*       outp = out   + (size_t)b * CO * hw + (size_t)h0 * WW + w;

    #pragma unroll
    for (int r = 0; r < THR; r++) {
        // ---- build A[d] = sum_ci in*phi_d(z),  Bv[d] = sum_ci phi_d(z) ----
        float A[DD], Bv[DD];
        #pragma unroll
        for (int d = 0; d < DD; d++) { A[d] = 0.f; Bv[d] = 0.f; }

        #pragma unroll
        for (int ci = 0; ci < CI; ci++) {
            float g = gup [ci * hw + (size_t)r * WW];
            float v = inpp[ci * hw + (size_t)r * WW];
            float zp = fminf(fmaxf(g * 7.0f, 0.0f), 7.0f);
            #pragma unroll
            for (int d = 0; d < DD; d++) {
                float wd = fmaxf(0.0f, 1.0f - fabsf(zp - (float)d));
                A[d]  = fmaf(v, wd, A[d]);
                Bv[d] += wd;
            }
        }

        unsigned long long AA[DD], BB[DD];
        #pragma unroll
        for (int d = 0; d < DD; d++) {
            AA[d] = pack2(A[d], A[d]);
            float bb = Bv[d] * 0.125f;   // mean over C_in
            BB[d] = pack2(bb, bb);
        }

        // ---- contract against 2 x-cells of y-folded coeffs ----
        const float* rowL = &gy[((r * NX + lx)     * DD) * 2 * CO];
        const float* rowR = &gy[((r * NX + lx + 1) * DD) * 2 * CO];

        unsigned long long tL0 = 0ull, tL1 = 0ull, tL2 = 0ull, tL3 = 0ull;
        unsigned long long tR0 = 0ull, tR1 = 0ull, tR2 = 0ull, tR3 = 0ull;

        #pragma unroll
        for (int d = 0; d < DD; d++) {
            // per (cell,d): 64 B = [w co0..7 | b co0..7]
            const ulonglong2* pL = reinterpret_cast<const ulonglong2*>(rowL + d * 16);
            const ulonglong2* pR = reinterpret_cast<const ulonglong2*>(rowR + d * 16);
            ulonglong2 wL = pL[0];   // w: (co0,co1),(co2,co3)
            ulonglong2 wl = pL[1];   // w: (co4,co5),(co6,co7)
            ulonglong2 bL = pL[2];   // b: (co0,co1),(co2,co3)
            ulonglong2 bl = pL[3];   // b: (co4,co5),(co6,co7)
            tL0 = ffma2(wL.x, AA[d], tL0);
            tL1 = ffma2(wL.y, AA[d], tL1);
            tL2 = ffma2(wl.x, AA[d], tL2);
            tL3 = ffma2(wl.y, AA[d], tL3);
            tL0 = ffma2(bL.x, BB[d], tL0);
            tL1 = ffma2(bL.y, BB[d], tL1);
            tL2 = ffma2(bl.x, BB[d], tL2);
            tL3 = ffma2(bl.y, BB[d], tL3);

            ulonglong2 wR = pR[0];
            ulonglong2 wr = pR[1];
            ulonglong2 bR = pR[2];
            ulonglong2 br = pR[3];
            tR0 = ffma2(wR.x, AA[d], tR0);
            tR1 = ffma2(wR.y, AA[d], tR1);
            tR2 = ffma2(wr.x, AA[d], tR2);
            tR3 = ffma2(wr.y, AA[d], tR3);
            tR0 = ffma2(bR.x, BB[d], tR0);
            tR1 = ffma2(bR.y, BB[d], tR1);
            tR2 = ffma2(br.x, BB[d], tR2);
            tR3 = ffma2(br.y, BB[d], tR3);
        }

        // out = (1-wx)*tL + wx*tR
        unsigned long long o0 = ffma2(tR0, WX, fmul2(tL0, WX1));
        unsigned long long o1 = ffma2(tR1, WX, fmul2(tL1, WX1));
        unsigned long long o2 = ffma2(tR2, WX, fmul2(tL2, WX1));
        unsigned long long o3 = ffma2(tR3, WX, fmul2(tL3, WX1));

        float2 f0 = unpack2(o0), f1 = unpack2(o1), f2 = unpack2(o2), f3 = unpack2(o3);
        outp[0 * hw + (size_t)r * WW] = f0.x;
        outp[1 * hw + (size_t)r * WW] = f0.y;
        outp[2 * hw + (size_t)r * WW] = f1.x;
        outp[3 * hw + (size_t)r * WW] = f1.y;
        outp[4 * hw + (size_t)r * WW] = f2.x;
        outp[5 * hw + (size_t)r * WW] = f2.y;
        outp[6 * hw + (size_t)r * WW] = f3.x;
        outp[7 * hw + (size_t)r * WW] = f3.y;
    }
}

extern "C" void kernel_launch(void* const* d_in, const int* in_sizes, int n_in,
                              void* d_out, int out_size) {
    const float* grid  = (const float*)d_in[0];   // (2,8,2,8,16,16)
    const float* guide = (const float*)d_in[1];   // (2,8,512,512)
    const float* inp   = (const float*)d_in[2];   // (2,8,512,512)
    float* out = (float*)d_out;                   // (2,8,512,512)

    dim3 g(WW / TW, HH / THR, Bn);   // (2, 128, 2) = 512 blocks
    bsa_kernel<<<g, TW>>>(grid, guide, inp, out);
}

// round 4
// speedup vs baseline: 1.6008x; 1.0750x over previous
#include <cuda_runtime.h>

#define Bn  2
#define CO  8
#define CI  8
#define DD  8
#define GH  16
#define GW  16
#define HH  512
#define WW  512
#define TW  256        // threads per block = tile width in pixels
#define THR 4          // tile height (rows)
#define NY  3
#define NX  10
#define CSTR 132       // floats per (r,xx) cell in gy: 8d*16 + 4 pad (bank shift)

#define GY_FLOATS   (THR * NX * CSTR)                 // 5280
#define SG_FLOATS   (NY * NX * 2 * DD * CO)           // 3840
#define BS_FLOATS   (2 * DD * TW * THR)               // 16384
#define SMEM_FLOATS (GY_FLOATS + BS_FLOATS)           // 21664
#define SMEM_BYTES  (SMEM_FLOATS * 4)                 // 86656 B

typedef unsigned long long ull;

__device__ __forceinline__ ull ffma2(ull a, ull b, ull c) {
    ull d;
    asm("fma.rn.f32x2 %0, %1, %2, %3;" : "=l"(d) : "l"(a), "l"(b), "l"(c));
    return d;
}
__device__ __forceinline__ ull pack2(float lo, float hi) {
    ull r;
    asm("mov.b64 %0, {%1, %2};" : "=l"(r) : "f"(lo), "f"(hi));
    return r;
}
__device__ __forceinline__ float2 unpack2(ull v) {
    float2 f;
    asm("mov.b64 {%0, %1}, %2;" : "=f"(f.x), "=f"(f.y) : "l"(v));
    return f;
}

__global__ __launch_bounds__(TW, 2) void bsa_kernel(
    const float* __restrict__ grid,
    const float* __restrict__ guide,
    const float* __restrict__ inp,
    float* __restrict__ out)
{
    extern __shared__ __align__(16) float sm[];
    float* gy = sm;                  // [r][xx][d*16 + k*8 + co], cell stride CSTR
    float* sg = sm + GY_FLOATS;      // raw grid slice (temp)
    float* bs = sm + GY_FLOATS;      // basis  [a][d][px]  (aliases sg)

    const int b  = blockIdx.z;
    const int w0 = blockIdx.x * TW;
    const int h0 = blockIdx.y * THR;
    const int t  = threadIdx.x;
    const float s = 15.0f / 511.0f;

    int ybase = (int)((float)h0 * s); if (ybase > GH - 2) ybase = GH - 2;
    int xbase = (int)((float)w0 * s); if (xbase > GW - 2) xbase = GW - 2;

    // ---- stage raw grid slice ----
    const float* gptr0 = grid + (size_t)b * (CO * 2 * DD * GH * GW);
    #pragma unroll
    for (int i = t; i < SG_FLOATS; i += TW) {
        int xx = i % NX;
        int r  = i / NX;
        int yy = r % NY;  r /= NY;
        int d  = r % DD;  r /= DD;
        int k  = r % 2;
        int co = r / 2;
        int gyy = ybase + yy; if (gyy > GH - 1) gyy = GH - 1;
        int gx  = xbase + xx; if (gx  > GW - 1) gx  = GW - 1;
        sg[(((yy * NX + xx) * 2 + k) * DD + d) * CO + co] =
            gptr0[(((co * 2 + k) * DD + d) * GH + gyy) * GW + gx];
    }
    __syncthreads();

    // ---- y-fold into gy ----
    #pragma unroll
    for (int j = t; j < THR * NX * DD * 16; j += TW) {
        int co = j & 7;
        int k  = (j >> 3) & 1;
        int d  = (j >> 4) & 7;
        int v  = j >> 7;           // r*NX + xx
        int xx = v % NX;
        int r  = v / NX;
        float yp = (float)(h0 + r) * s;
        int   y0 = (int)yp; if (y0 > GH - 2) y0 = GH - 2;
        float wy = yp - (float)y0;
        int   ly = y0 - ybase;
        float v0 = sg[(((ly       * NX + xx) * 2 + k) * DD + d) * CO + co];
        float v1 = sg[((((ly + 1) * NX + xx) * 2 + k) * DD + d) * CO + co];
        gy[(r * NX + xx) * CSTR + d * 16 + k * 8 + co] = v0 + wy * (v1 - v0);
    }
    __syncthreads();

    // ---- phase 1: z-basis per pixel -> bs (overwrites sg region) ----
    {
        const size_t hw = (size_t)HH * WW;
        const float* gup  = guide + (size_t)b * CI * hw + (size_t)h0 * WW + w0 + t;
        const float* inpp = inp   + (size_t)b * CI * hw + (size_t)h0 * WW + w0 + t;
        #pragma unroll
        for (int r = 0; r < THR; r++) {
            float A[DD], Bv[DD];
            #pragma unroll
            for (int d = 0; d < DD; d++) { A[d] = 0.f; Bv[d] = 0.f; }
            #pragma unroll
            for (int ci = 0; ci < CI; ci++) {
                float g = gup [ci * hw + (size_t)r * WW];
                float v = inpp[ci * hw + (size_t)r * WW];
                float zp = fminf(fmaxf(g * 7.0f, 0.0f), 7.0f);
                #pragma unroll
                for (int d = 0; d < DD; d++) {
                    float wd = fmaxf(0.0f, 1.0f - fabsf(zp - (float)d));
                    A[d]  = fmaf(v, wd, A[d]);
                    Bv[d] += wd;
                }
            }
            const int px = r * TW + t;
            #pragma unroll
            for (int d = 0; d < DD; d++) {
                bs[d * (TW * THR) + px]                   = A[d];
                bs[(DD + d) * (TW * THR) + px]            = Bv[d] * 0.125f;
            }
        }
    }
    __syncthreads();

    // ---- phase 2: 4 px x 8 co per thread, 3-cell u-basis ----
    const int r  = t >> 6;
    const int g  = (t & 63) << 2;   // start column within tile

    float u[3][4];
    int x00 = 0;
    #pragma unroll
    for (int j = 0; j < 4; j++) {
        float xp = (float)(w0 + g + j) * s;
        int   x0 = (int)xp; if (x0 > GW - 2) x0 = GW - 2;
        float wx = xp - (float)x0;
        if (j == 0) x00 = x0;
        int c = x0 - x00;           // 0 or 1
        u[0][j] = (c == 0) ? (1.0f - wx) : 0.0f;
        u[1][j] = (c == 0) ? wx          : (1.0f - wx);
        u[2][j] = (c == 0) ? 0.0f        : wx;
    }
    const int lx0 = x00 - xbase;
    const float* cell0 = gy + (r * NX + lx0) * CSTR;

    ull acc[4][4];
    #pragma unroll
    for (int j = 0; j < 4; j++)
        #pragma unroll
        for (int p = 0; p < 4; p++) acc[j][p] = 0ull;

    const float* bsa = bs + r * TW + g;

    #pragma unroll
    for (int d = 0; d < DD; d++) {
        float4 Af = *reinterpret_cast<const float4*>(bsa + d * (TW * THR));
        float4 Bf = *reinterpret_cast<const float4*>(bsa + (DD + d) * (TW * THR));
        float Aj[4] = {Af.x, Af.y, Af.z, Af.w};
        float Bj[4] = {Bf.x, Bf.y, Bf.z, Bf.w};

        #pragma unroll
        for (int c = 0; c < 3; c++) {
            const ulonglong2* p =
                reinterpret_cast<const ulonglong2*>(cell0 + c * CSTR + d * 16);
            ulonglong2 w01 = p[0];   // W co0..3
            ulonglong2 w23 = p[1];   // W co4..7
            ulonglong2 b01 = p[2];   // B co0..3
            ulonglong2 b23 = p[3];   // B co4..7
            #pragma unroll
            for (int j = 0; j < 4; j++) {
                float uu = u[c][j];
                float au = Aj[j] * uu;
                float bu = Bj[j] * uu;
                ull AU = pack2(au, au);
                ull BU = pack2(bu, bu);
                acc[j][0] = ffma2(w01.x, AU, acc[j][0]);
                acc[j][1] = ffma2(w01.y, AU, acc[j][1]);
                acc[j][2] = ffma2(w23.x, AU, acc[j][2]);
                acc[j][3] = ffma2(w23.y, AU, acc[j][3]);
                acc[j][0] = ffma2(b01.x, BU, acc[j][0]);
                acc[j][1] = ffma2(b01.y, BU, acc[j][1]);
                acc[j][2] = ffma2(b23.x, BU, acc[j][2]);
                acc[j][3] = ffma2(b23.y, BU, acc[j][3]);
            }
        }
    }

    // ---- epilogue: transpose to [co][4px] and STG.128 per co ----
    const size_t hw = (size_t)HH * WW;
    float* op = out + (size_t)b * CO * hw + (size_t)(h0 + r) * WW + w0 + g;

    float vals[4][8];   // [px][co]
    #pragma unroll
    for (int j = 0; j < 4; j++) {
        #pragma unroll
        for (int p = 0; p < 4; p++) {
            float2 f = unpack2(acc[j][p]);
            vals[j][2 * p]     = f.x;
            vals[j][2 * p + 1] = f.y;
        }
    }
    #pragma unroll
    for (int co = 0; co < CO; co++) {
        float4 q = make_float4(vals[0][co], vals[1][co], vals[2][co], vals[3][co]);
        *reinterpret_cast<float4*>(op + (size_t)co * hw) = q;
    }
}

extern "C" void kernel_launch(void* const* d_in, const int* in_sizes, int n_in,
                              void* d_out, int out_size) {
    const float* grid  = (const float*)d_in[0];   // (2,8,2,8,16,16)
    const float* guide = (const float*)d_in[1];   // (2,8,512,512)
    const float* inp   = (const float*)d_in[2];   // (2,8,512,512)
    float* out = (float*)d_out;                   // (2,8,512,512)

    cudaFuncSetAttribute(bsa_kernel,
                         cudaFuncAttributeMaxDynamicSharedMemorySize, SMEM_BYTES);

    dim3 gdim(WW / TW, HH / THR, Bn);   // (2, 128, 2) = 512 blocks
    bsa_kernel<<<gdim, TW, SMEM_BYTES>>>(grid, guide, inp, out);
}

// round 5
// speedup vs baseline: 1.6707x; 1.0437x over previous
#include <cuda_runtime.h>

#define Bn  2
#define CO  8
#define CI  8
#define DD  8
#define GH  16
#define GW  16
#define HH  512
#define WW  512
#define TW  256        // threads per block = tile width in pixels
#define THR 4          // tile height (rows)
#define NY  3
#define NX  10
#define CSTR 132       // floats per (r,xx) cell in gy

#define BSTR 1152      // float2 elements per d-plane in bs (1024 px + swizzle pad)
#define GY_FLOATS   (THR * NX * CSTR)                 // 5280
#define SG_FLOATS   (NY * NX * 2 * DD * CO)           // 3840
#define BS_F2       (DD * BSTR)                        // 9216 float2 = 73728 B
#define SMEM_BYTES  (GY_FLOATS * 4 + BS_F2 * 8)        // 94848 B

typedef unsigned long long ull;

__device__ __forceinline__ ull ffma2(ull a, ull b, ull c) {
    ull d;
    asm("fma.rn.f32x2 %0, %1, %2, %3;" : "=l"(d) : "l"(a), "l"(b), "l"(c));
    return d;
}
__device__ __forceinline__ ull pack2(float lo, float hi) {
    ull r;
    asm("mov.b64 %0, {%1, %2};" : "=l"(r) : "f"(lo), "f"(hi));
    return r;
}
__device__ __forceinline__ float2 unpack2(ull v) {
    float2 f;
    asm("mov.b64 {%0, %1}, %2;" : "=f"(f.x), "=f"(f.y) : "l"(v));
    return f;
}

__global__ __launch_bounds__(TW, 2) void bsa_kernel(
    const float* __restrict__ grid,
    const float* __restrict__ guide,
    const float* __restrict__ inp,
    float* __restrict__ out)
{
    extern __shared__ __align__(16) float sm[];
    float*  gy  = sm;                                  // y-folded coeffs
    float*  sg  = sm + GY_FLOATS;                      // raw grid slice (temp)
    float2* bsp = reinterpret_cast<float2*>(sm + GY_FLOATS);  // basis (aliases sg)

    const int b  = blockIdx.z;
    const int w0 = blockIdx.x * TW;
    const int h0 = blockIdx.y * THR;
    const int t  = threadIdx.x;
    const float s = 15.0f / 511.0f;

    int ybase = (int)((float)h0 * s); if (ybase > GH - 2) ybase = GH - 2;
    int xbase = (int)((float)w0 * s); if (xbase > GW - 2) xbase = GW - 2;

    // ---- stage raw grid slice ----
    const float* gptr0 = grid + (size_t)b * (CO * 2 * DD * GH * GW);
    #pragma unroll
    for (int i = t; i < SG_FLOATS; i += TW) {
        int xx = i % NX;
        int r  = i / NX;
        int yy = r % NY;  r /= NY;
        int d  = r % DD;  r /= DD;
        int k  = r % 2;
        int co = r / 2;
        int gyy = ybase + yy; if (gyy > GH - 1) gyy = GH - 1;
        int gx  = xbase + xx; if (gx  > GW - 1) gx  = GW - 1;
        sg[(((yy * NX + xx) * 2 + k) * DD + d) * CO + co] =
            gptr0[(((co * 2 + k) * DD + d) * GH + gyy) * GW + gx];
    }
    __syncthreads();

    // ---- y-fold into gy; fold 1/8 bias mean into k==1 coefficients ----
    #pragma unroll
    for (int j = t; j < THR * NX * DD * 16; j += TW) {
        int co = j & 7;
        int k  = (j >> 3) & 1;
        int d  = (j >> 4) & 7;
        int v  = j >> 7;           // r*NX + xx
        int xx = v % NX;
        int r  = v / NX;
        float yp = (float)(h0 + r) * s;
        int   y0 = (int)yp; if (y0 > GH - 2) y0 = GH - 2;
        float wy = yp - (float)y0;
        int   ly = y0 - ybase;
        float v0 = sg[(((ly       * NX + xx) * 2 + k) * DD + d) * CO + co];
        float v1 = sg[((((ly + 1) * NX + xx) * 2 + k) * DD + d) * CO + co];
        float val = v0 + wy * (v1 - v0);
        val *= (k ? 0.125f : 1.0f);
        gy[(r * NX + xx) * CSTR + d * 16 + k * 8 + co] = val;
    }
    __syncthreads();

    // ---- phase 1: z-basis scatter-accumulate into bs (aliases sg) ----
    // bs layout: plane d, physical float2 index phys(px) = px + 2*(px>>4)
    {
        const size_t hw = (size_t)HH * WW;
        const float* gup  = guide + (size_t)b * CI * hw + (size_t)h0 * WW + w0 + t;
        const float* inpp = inp   + (size_t)b * CI * hw + (size_t)h0 * WW + w0 + t;
        const int physt = t + ((t >> 4) << 1);
        #pragma unroll
        for (int r = 0; r < THR; r++) {
            float2* col = bsp + (r * 288 + physt);   // r*256 px -> r*288 phys
            #pragma unroll
            for (int d = 0; d < DD; d++) col[d * BSTR] = make_float2(0.f, 0.f);

            #pragma unroll
            for (int ci = 0; ci < CI; ci++) {
                float g = gup [ci * hw + (size_t)r * WW];
                float v = inpp[ci * hw + (size_t)r * WW];
                float zp = fminf(fmaxf(g * 7.0f, 0.0f), 7.0f);
                int d0 = (int)zp; if (d0 > 6) d0 = 6;
                float f  = zp - (float)d0;
                float vf = v * f;
                float v1 = v - vf;       // v*(1-f)
                float f1 = 1.0f - f;
                float2* p = col + d0 * BSTR;
                float2 a0 = p[0];
                a0.x += v1; a0.y += f1;
                p[0] = a0;
                float2 a1 = p[BSTR];
                a1.x += vf; a1.y += f;
                p[BSTR] = a1;
            }
        }
    }
    __syncthreads();

    // ---- phase 2: 4 px x 8 co per thread, 3-cell u-basis ----
    const int r  = t >> 6;
    const int g  = (t & 63) << 2;   // start column within tile

    float u[3][4];
    int x00 = 0;
    #pragma unroll
    for (int j = 0; j < 4; j++) {
        float xp = (float)(w0 + g + j) * s;
        int   x0 = (int)xp; if (x0 > GW - 2) x0 = GW - 2;
        float wx = xp - (float)x0;
        if (j == 0) x00 = x0;
        int c = x0 - x00;           // 0 or 1
        u[0][j] = (c == 0) ? (1.0f - wx) : 0.0f;
        u[1][j] = (c == 0) ? wx          : (1.0f - wx);
        u[2][j] = (c == 0) ? 0.0f        : wx;
    }
    const int lx0 = x00 - xbase;
    const float* cell0 = gy + (r * NX + lx0) * CSTR;

    ull acc[4][4];
    #pragma unroll
    for (int j = 0; j < 4; j++)
        #pragma unroll
        for (int p = 0; p < 4; p++) acc[j][p] = 0ull;

    const int physb = r * 288 + g + ((g >> 4) << 1);

    #pragma unroll
    for (int d = 0; d < DD; d++) {
        const float4* q = reinterpret_cast<const float4*>(bsp + d * BSTR + physb);
        float4 qa = q[0];   // (A0,B0,A1,B1)
        float4 qb = q[1];   // (A2,B2,A3,B3)
        float Aj[4] = {qa.x, qa.z, qb.x, qb.z};
        float Bj[4] = {qa.y, qa.w, qb.y, qb.w};

        #pragma unroll
        for (int c = 0; c < 3; c++) {
            const ulonglong2* p =
                reinterpret_cast<const ulonglong2*>(cell0 + c * CSTR + d * 16);
            ulonglong2 w01 = p[0];   // W co0..3
            ulonglong2 w23 = p[1];   // W co4..7
            ulonglong2 b01 = p[2];   // B co0..3 (pre-scaled by 1/8)
            ulonglong2 b23 = p[3];   // B co4..7
            #pragma unroll
            for (int j = 0; j < 4; j++) {
                float uu = u[c][j];
                float au = Aj[j] * uu;
                float bu = Bj[j] * uu;
                ull AU = pack2(au, au);
                ull BU = pack2(bu, bu);
                acc[j][0] = ffma2(w01.x, AU, acc[j][0]);
                acc[j][1] = ffma2(w01.y, AU, acc[j][1]);
                acc[j][2] = ffma2(w23.x, AU, acc[j][2]);
                acc[j][3] = ffma2(w23.y, AU, acc[j][3]);
                acc[j][0] = ffma2(b01.x, BU, acc[j][0]);
                acc[j][1] = ffma2(b01.y, BU, acc[j][1]);
                acc[j][2] = ffma2(b23.x, BU, acc[j][2]);
                acc[j][3] = ffma2(b23.y, BU, acc[j][3]);
            }
        }
    }

    // ---- epilogue: transpose to [co][4px] and STG.128 per co ----
    const size_t hw = (size_t)HH * WW;
    float* op = out + (size_t)b * CO * hw + (size_t)(h0 + r) * WW + w0 + g;

    float vals[4][8];   // [px][co]
    #pragma unroll
    for (int j = 0; j < 4; j++) {
        #pragma unroll
        for (int p = 0; p < 4; p++) {
            float2 f = unpack2(acc[j][p]);
            vals[j][2 * p]     = f.x;
            vals[j][2 * p + 1] = f.y;
        }
    }
    #pragma unroll
    for (int co = 0; co < CO; co++) {
        float4 q = make_float4(vals[0][co], vals[1][co], vals[2][co], vals[3][co]);
        *reinterpret_cast<float4*>(op + (size_t)co * hw) = q;
    }
}

extern "C" void kernel_launch(void* const* d_in, const int* in_sizes, int n_in,
                              void* d_out, int out_size) {
    const float* grid  = (const float*)d_in[0];   // (2,8,2,8,16,16)
    const float* guide = (const float*)d_in[1];   // (2,8,512,512)
    const float* inp   = (const float*)d_in[2];   // (2,8,512,512)
    float* out = (float*)d_out;                   // (2,8,512,512)

    cudaFuncSetAttribute(bsa_kernel,
                         cudaFuncAttributeMaxDynamicSharedMemorySize, SMEM_BYTES);

    dim3 gdim(WW / TW, HH / THR, Bn);   // (2, 128, 2) = 512 blocks
    bsa_kernel<<<gdim, TW, SMEM_BYTES>>>(grid, guide, inp, out);
}